// round 2
// baseline (speedup 1.0000x reference)
#include <cuda_runtime.h>
#include <cuda_bf16.h>
#include <cstdint>

// ============================================================================
// RBM CD-k loss, exact JAX-threefry reproduction.
// B=16384, D=4096, H=128, k=4.
//
// RNG_MODE: 1 = jax_threefry_partitionable=True (32-bit path: out0^out1 of
//               threefry2x32(key, (hi32(i), lo32(i))), i = linear index)
//           0 = legacy original mode (split-counter halves)
//           2 = partitionable but taking word0 (fallback hypothesis)
// ============================================================================
#define RNG_MODE 1

#define RBM_B 16384
#define RBM_D 4096
#define RBM_H 128

// Scratch (allocation-free rule: __device__ globals)
__device__ float  g_xi[(size_t)RBM_B * RBM_D];   // current visible sample (268MB)
__device__ float  g_h [(size_t)RBM_B * RBM_H];   // hidden sample (8MB)
__device__ double g_acc[4];  // [0]=sum softplus(x), [1]=sum softplus(x_rec),
                             // [2]=dot(x,bx), [3]=dot(x_rec,bx)

// ---------------------------------------------------------------------------
// Threefry-2x32 (20 rounds), matches jax._src.prng
// ---------------------------------------------------------------------------
__device__ __forceinline__ uint2 tf2x32_dev(uint32_t k0, uint32_t k1,
                                            uint32_t x0, uint32_t x1) {
    uint32_t ks2 = k0 ^ k1 ^ 0x1BD11BDAu;
    x0 += k0; x1 += k1;
#define TF_MIX(r) { x0 += x1; x1 = __funnelshift_l(x1, x1, (r)); x1 ^= x0; }
    TF_MIX(13) TF_MIX(15) TF_MIX(26) TF_MIX(6)   x0 += k1;  x1 += ks2 + 1u;
    TF_MIX(17) TF_MIX(29) TF_MIX(16) TF_MIX(24)  x0 += ks2; x1 += k0  + 2u;
    TF_MIX(13) TF_MIX(15) TF_MIX(26) TF_MIX(6)   x0 += k0;  x1 += k1  + 3u;
    TF_MIX(17) TF_MIX(29) TF_MIX(16) TF_MIX(24)  x0 += k1;  x1 += ks2 + 4u;
    TF_MIX(13) TF_MIX(15) TF_MIX(26) TF_MIX(6)   x0 += ks2; x1 += k0  + 5u;
#undef TF_MIX
    return make_uint2(x0, x1);
}

// uniform in [0,1) exactly as jax._src.random._uniform (f32: bits>>9 | 1.0f, -1)
// idx < 2^32 for all arrays here, so counter hi word is 0.
__device__ __forceinline__ float tf_uniform(uint32_t k0, uint32_t k1,
                                            uint32_t idx, uint32_t half) {
    uint32_t bits;
#if RNG_MODE == 1
    uint2 o = tf2x32_dev(k0, k1, 0u, idx);
    bits = o.x ^ o.y;
    (void)half;
#elif RNG_MODE == 2
    uint2 o = tf2x32_dev(k0, k1, 0u, idx);
    bits = o.x;
    (void)half;
#else
    if (idx < half) { uint2 o = tf2x32_dev(k0, k1, idx, idx + half); bits = o.x; }
    else            { uint2 o = tf2x32_dev(k0, k1, idx - half, idx); bits = o.y; }
#endif
    return __uint_as_float((bits >> 9) | 0x3f800000u) - 1.0f;
}

__device__ __forceinline__ float sigmoid_f(float x) {
    return 1.0f / (1.0f + expf(-x));
}
__device__ __forceinline__ float softplus_f(float x) {
    return fmaxf(x, 0.0f) + log1pf(expf(-fabsf(x)));
}

// ---------------------------------------------------------------------------
// Block-level sum -> atomicAdd(double)
// ---------------------------------------------------------------------------
__device__ __forceinline__ void block_acc_add(float local, int slot) {
    __shared__ float red[8];
    int lane = threadIdx.x & 31, wid = threadIdx.x >> 5;
    #pragma unroll
    for (int off = 16; off; off >>= 1)
        local += __shfl_xor_sync(0xffffffffu, local, off);
    if (lane == 0) red[wid] = local;
    __syncthreads();
    if (threadIdx.x == 0) {
        double s = 0.0;
        #pragma unroll
        for (int i = 0; i < 8; i++) s += (double)red[i];
        atomicAdd(&g_acc[slot], s);
    }
}

// ---------------------------------------------------------------------------
// Hidden-side GEMM: wx[b,j] = sum_i X[b,i]*W[i,j] + bh[j]
//   doSample: g_h[b,j] = (u < sigmoid(wx)) with key (k0,k1)
//   accIdx>=0: accumulate softplus(wx) into g_acc[accIdx]
// grid = B/128 blocks, 256 threads, 8x8 microtile, K-chunk 32.
// ---------------------------------------------------------------------------
__global__ void __launch_bounds__(256)
rbm_hidden_kernel(const float* __restrict__ Xext,   // null -> g_xi
                  const float* __restrict__ W,
                  const float* __restrict__ bh,
                  uint32_t k0, uint32_t k1, int doSample, int accIdx) {
    const float* __restrict__ X = Xext ? Xext : g_xi;
    __shared__ float xs[32][132];   // [k][row]  (transposed)
    __shared__ float ws[32][132];   // [k][col]
    const int tid = threadIdx.x;
    const int tx = tid & 15, ty = tid >> 4;
    const int b0 = blockIdx.x * 128;

    float acc[8][8];
    #pragma unroll
    for (int r = 0; r < 8; r++)
        #pragma unroll
        for (int c = 0; c < 8; c++) acc[r][c] = 0.0f;

    for (int kc = 0; kc < RBM_D; kc += 32) {
        // load X tile 128x32 -> xs[k][row]
        #pragma unroll
        for (int p = 0; p < 4; p++) {
            int idx4 = tid + p * 256;
            int row = idx4 >> 3, kq = idx4 & 7;
            float4 v = *(const float4*)&X[(size_t)(b0 + row) * RBM_D + kc + kq * 4];
            xs[kq * 4 + 0][row] = v.x; xs[kq * 4 + 1][row] = v.y;
            xs[kq * 4 + 2][row] = v.z; xs[kq * 4 + 3][row] = v.w;
        }
        // load W tile 32x128 -> ws[k][j]
        #pragma unroll
        for (int p = 0; p < 4; p++) {
            int idx4 = tid + p * 256;
            int k = idx4 >> 5, j4 = idx4 & 31;
            float4 v = *(const float4*)&W[(size_t)(kc + k) * RBM_H + j4 * 4];
            *(float4*)&ws[k][j4 * 4] = v;
        }
        __syncthreads();
        #pragma unroll 8
        for (int k = 0; k < 32; k++) {
            float4 a0 = *(float4*)&xs[k][ty * 8], a1 = *(float4*)&xs[k][ty * 8 + 4];
            float4 c0 = *(float4*)&ws[k][tx * 8], c1 = *(float4*)&ws[k][tx * 8 + 4];
            float av[8] = {a0.x, a0.y, a0.z, a0.w, a1.x, a1.y, a1.z, a1.w};
            float bv[8] = {c0.x, c0.y, c0.z, c0.w, c1.x, c1.y, c1.z, c1.w};
            #pragma unroll
            for (int r = 0; r < 8; r++)
                #pragma unroll
                for (int c = 0; c < 8; c++) acc[r][c] = fmaf(av[r], bv[c], acc[r][c]);
        }
        __syncthreads();
    }

    float fe_local = 0.0f;
    #pragma unroll
    for (int r = 0; r < 8; r++) {
        int row = b0 + ty * 8 + r;
        #pragma unroll
        for (int c = 0; c < 8; c++) {
            int col = tx * 8 + c;
            float wx = acc[r][c] + bh[col];
            if (doSample) {
                float pg = sigmoid_f(wx);
                uint32_t idx = (uint32_t)(row * RBM_H + col);
                float u = tf_uniform(k0, k1, idx, (uint32_t)(RBM_B * RBM_H) / 2u);
                g_h[(size_t)row * RBM_H + col] = (u < pg) ? 1.0f : 0.0f;
            }
            if (accIdx >= 0) fe_local += softplus_f(wx);
        }
    }
    if (accIdx >= 0) block_acc_add(fe_local, accIdx);
}

// ---------------------------------------------------------------------------
// Visible-side GEMM: wx[b,d] = sum_j g_h[b,j]*W[d,j] + bx[d]
//   g_xi[b,d] = (u < sigmoid(wx)) with key (k0,k1)
// grid = (D/128, B/128), 256 threads, 8x8 microtile, K=128 in 4 chunks.
// ---------------------------------------------------------------------------
__global__ void __launch_bounds__(256)
rbm_visible_kernel(const float* __restrict__ W,
                   const float* __restrict__ bx,
                   uint32_t k0, uint32_t k1) {
    __shared__ float hs[32][132];   // [k][brow]
    __shared__ float wv[32][132];   // [k][dcol]  (W transposed)
    const int tid = threadIdx.x;
    const int tx = tid & 15, ty = tid >> 4;
    const int d0 = blockIdx.x * 128;
    const int b0 = blockIdx.y * 128;

    float acc[8][8];
    #pragma unroll
    for (int r = 0; r < 8; r++)
        #pragma unroll
        for (int c = 0; c < 8; c++) acc[r][c] = 0.0f;

    #pragma unroll
    for (int kc = 0; kc < RBM_H; kc += 32) {
        #pragma unroll
        for (int p = 0; p < 4; p++) {
            int idx4 = tid + p * 256;
            int row = idx4 >> 3, kq = idx4 & 7;
            float4 v = *(const float4*)&g_h[(size_t)(b0 + row) * RBM_H + kc + kq * 4];
            hs[kq * 4 + 0][row] = v.x; hs[kq * 4 + 1][row] = v.y;
            hs[kq * 4 + 2][row] = v.z; hs[kq * 4 + 3][row] = v.w;
        }
        #pragma unroll
        for (int p = 0; p < 4; p++) {
            int idx4 = tid + p * 256;
            int dl = idx4 >> 3, kq = idx4 & 7;
            float4 v = *(const float4*)&W[(size_t)(d0 + dl) * RBM_H + kc + kq * 4];
            wv[kq * 4 + 0][dl] = v.x; wv[kq * 4 + 1][dl] = v.y;
            wv[kq * 4 + 2][dl] = v.z; wv[kq * 4 + 3][dl] = v.w;
        }
        __syncthreads();
        #pragma unroll 8
        for (int k = 0; k < 32; k++) {
            float4 a0 = *(float4*)&hs[k][ty * 8], a1 = *(float4*)&hs[k][ty * 8 + 4];
            float4 c0 = *(float4*)&wv[k][tx * 8], c1 = *(float4*)&wv[k][tx * 8 + 4];
            float av[8] = {a0.x, a0.y, a0.z, a0.w, a1.x, a1.y, a1.z, a1.w};
            float bv[8] = {c0.x, c0.y, c0.z, c0.w, c1.x, c1.y, c1.z, c1.w};
            #pragma unroll
            for (int r = 0; r < 8; r++)
                #pragma unroll
                for (int c = 0; c < 8; c++) acc[r][c] = fmaf(av[r], bv[c], acc[r][c]);
        }
        __syncthreads();
    }

    #pragma unroll
    for (int r = 0; r < 8; r++) {
        int b = b0 + ty * 8 + r;
        #pragma unroll
        for (int c = 0; c < 8; c++) {
            int d = d0 + tx * 8 + c;
            float wx = acc[r][c] + bx[d];
            float pg = sigmoid_f(wx);
            uint32_t idx = (uint32_t)b * (uint32_t)RBM_D + (uint32_t)d;
            float u = tf_uniform(k0, k1, idx, (uint32_t)((size_t)RBM_B * RBM_D / 2));
            g_xi[(size_t)b * RBM_D + d] = (u < pg) ? 1.0f : 0.0f;
        }
    }
}

// ---------------------------------------------------------------------------
// dot(v, broadcast bx) accumulated into g_acc[slot]
// ---------------------------------------------------------------------------
__global__ void __launch_bounds__(256)
rbm_dotbx_kernel(const float* __restrict__ vext,  // null -> g_xi
                 const float* __restrict__ bx, int slot) {
    const float* __restrict__ v = vext ? vext : g_xi;
    const size_t total = (size_t)RBM_B * RBM_D;
    float local = 0.0f;
    for (size_t i = (size_t)blockIdx.x * blockDim.x + threadIdx.x;
         i < total; i += (size_t)gridDim.x * blockDim.x)
        local += v[i] * bx[i & (RBM_D - 1)];
    block_acc_add(local, slot);
}

__global__ void rbm_init_kernel() {
    if (threadIdx.x < 4) g_acc[threadIdx.x] = 0.0;
}

// cd = [(-spx - dx) - (-spr - dr)] / B = (spr + dr - spx - dx)/B
__global__ void rbm_final_kernel(float* out) {
    out[0] = (float)((g_acc[1] + g_acc[3] - g_acc[0] - g_acc[2]) * (1.0 / (double)RBM_B));
}

// ---------------------------------------------------------------------------
// Host: threefry for fold_in subkeys.  key(42) = (0,42); fold_in(key, i) =
// threefry2x32(key, (0, i)) -> new key pair.
// ---------------------------------------------------------------------------
static inline uint32_t h_rotl(uint32_t v, int r) { return (v << r) | (v >> (32 - r)); }
static void h_tf2x32(uint32_t k0, uint32_t k1, uint32_t x0, uint32_t x1,
                     uint32_t* o0, uint32_t* o1) {
    uint32_t ks2 = k0 ^ k1 ^ 0x1BD11BDAu;
    x0 += k0; x1 += k1;
    static const int R0[4] = {13, 15, 26, 6}, R1[4] = {17, 29, 16, 24};
    auto round4 = [&](const int* R) {
        for (int i = 0; i < 4; i++) { x0 += x1; x1 = h_rotl(x1, R[i]); x1 ^= x0; }
    };
    round4(R0); x0 += k1;  x1 += ks2 + 1u;
    round4(R1); x0 += ks2; x1 += k0  + 2u;
    round4(R0); x0 += k0;  x1 += k1  + 3u;
    round4(R1); x0 += k1;  x1 += ks2 + 4u;
    round4(R0); x0 += ks2; x1 += k0  + 5u;
    *o0 = x0; *o1 = x1;
}

extern "C" void kernel_launch(void* const* d_in, const int* in_sizes, int n_in,
                              void* d_out, int out_size) {
    const float* x  = (const float*)d_in[0];   // [B, D] binary f32
    const float* W  = (const float*)d_in[1];   // [D, H]
    const float* bx = (const float*)d_in[2];   // [D]
    const float* bh = (const float*)d_in[3];   // [H]
    // nb_gibbs_steps is always 4 for this problem instance.
    const int NSTEP = 4;
    float* out = (float*)d_out;

    // subkeys: fold_in(key(42), i) for i = 0..2*NSTEP-1
    uint32_t kk[8][2];
    for (int i = 0; i < 2 * NSTEP; i++)
        h_tf2x32(0u, 42u, 0u, (uint32_t)i, &kk[i][0], &kk[i][1]);

    dim3 hblk(256), hgrd(RBM_B / 128);
    dim3 vblk(256), vgrd(RBM_D / 128, RBM_B / 128);

    rbm_init_kernel<<<1, 32>>>();

    // step 0: hidden from external x, sample h, and accumulate F(x) softplus
    rbm_hidden_kernel<<<hgrd, hblk>>>(x, W, bh, kk[0][0], kk[0][1], 1, 0);
    rbm_visible_kernel<<<vgrd, vblk>>>(W, bx, kk[1][0], kk[1][1]);
    // steps 1..3
    for (int s = 1; s < NSTEP; s++) {
        rbm_hidden_kernel<<<hgrd, hblk>>>(nullptr, W, bh, kk[2 * s][0], kk[2 * s][1], 1, -1);
        rbm_visible_kernel<<<vgrd, vblk>>>(W, bx, kk[2 * s + 1][0], kk[2 * s + 1][1]);
    }
    // free energy of x_rec (no sampling)
    rbm_hidden_kernel<<<hgrd, hblk>>>(nullptr, W, bh, 0u, 0u, 0, 1);
    // bias dot terms
    rbm_dotbx_kernel<<<2048, 256>>>(x, bx, 2);
    rbm_dotbx_kernel<<<2048, 256>>>(nullptr, bx, 3);

    rbm_final_kernel<<<1, 1>>>(out);
}

// round 4
// speedup vs baseline: 1.9314x; 1.9314x over previous
#include <cuda_runtime.h>
#include <cuda_bf16.h>
#include <cstdint>

// ============================================================================
// RBM CD-k loss on tensor cores (mma.sync bf16, exact 3-term W split).
// B=16384, D=4096, H=128, k=4.  RNG: jax threefry partitionable (verified R2).
// ============================================================================
#define RBM_B 16384
#define RBM_D 4096
#define RBM_H 128

// Scratch (__device__ globals per allocation rules)
__device__ __nv_bfloat16 g_xb[(size_t)RBM_B * RBM_D];   // bf16 copy of x
__device__ __nv_bfloat16 g_xi[(size_t)RBM_B * RBM_D];   // chain visible state
__device__ __nv_bfloat16 g_h [(size_t)RBM_B * RBM_H];   // hidden sample
__device__ __nv_bfloat16 g_Wp [3][(size_t)RBM_D * RBM_H];  // W split  [d*H+h]
__device__ __nv_bfloat16 g_Wtp[3][(size_t)RBM_H * RBM_D];  // W^T split [h*D+d]
__device__ double g_acc[4];  // [0]=softplus(x) [1]=softplus(xrec) [2]=x.bx [3]=xrec.bx

// ---------------------------------------------------------------------------
// Threefry-2x32 (jax partitionable mode, verified rel_err 9.2e-7)
// ---------------------------------------------------------------------------
__device__ __forceinline__ uint2 tf2x32_dev(uint32_t k0, uint32_t k1,
                                            uint32_t x0, uint32_t x1) {
    uint32_t ks2 = k0 ^ k1 ^ 0x1BD11BDAu;
    x0 += k0; x1 += k1;
#define TF_MIX(r) { x0 += x1; x1 = __funnelshift_l(x1, x1, (r)); x1 ^= x0; }
    TF_MIX(13) TF_MIX(15) TF_MIX(26) TF_MIX(6)   x0 += k1;  x1 += ks2 + 1u;
    TF_MIX(17) TF_MIX(29) TF_MIX(16) TF_MIX(24)  x0 += ks2; x1 += k0  + 2u;
    TF_MIX(13) TF_MIX(15) TF_MIX(26) TF_MIX(6)   x0 += k0;  x1 += k1  + 3u;
    TF_MIX(17) TF_MIX(29) TF_MIX(16) TF_MIX(24)  x0 += k1;  x1 += ks2 + 4u;
    TF_MIX(13) TF_MIX(15) TF_MIX(26) TF_MIX(6)   x0 += ks2; x1 += k0  + 5u;
#undef TF_MIX
    return make_uint2(x0, x1);
}
__device__ __forceinline__ float tf_uniform(uint32_t k0, uint32_t k1, uint32_t idx) {
    uint2 o = tf2x32_dev(k0, k1, 0u, idx);
    uint32_t bits = o.x ^ o.y;
    return __uint_as_float((bits >> 9) | 0x3f800000u) - 1.0f;
}
__device__ __forceinline__ float sigmoid_f(float x) { return 1.0f / (1.0f + expf(-x)); }
__device__ __forceinline__ float softplus_f(float x) {
    return fmaxf(x, 0.0f) + log1pf(expf(-fabsf(x)));
}

__device__ __forceinline__ void block_acc_add(float local, int slot) {
    __shared__ float red[8];
    int lane = threadIdx.x & 31, wid = threadIdx.x >> 5;
    #pragma unroll
    for (int off = 16; off; off >>= 1)
        local += __shfl_xor_sync(0xffffffffu, local, off);
    if (lane == 0) red[wid] = local;
    __syncthreads();
    if (threadIdx.x == 0) {
        double s = 0.0;
        #pragma unroll
        for (int i = 0; i < 8; i++) s += (double)red[i];
        atomicAdd(&g_acc[slot], s);
    }
}

// ---------------------------------------------------------------------------
// mma / ldmatrix helpers
// ---------------------------------------------------------------------------
__device__ __forceinline__ uint32_t smem_u32(const void* p) {
    uint32_t a;
    asm("{ .reg .u64 t; cvta.to.shared.u64 t, %1; cvt.u32.u64 %0, t; }"
        : "=r"(a) : "l"(p));
    return a;
}
__device__ __forceinline__ void ldsm_x4(uint32_t a, uint32_t& r0, uint32_t& r1,
                                        uint32_t& r2, uint32_t& r3) {
    asm volatile("ldmatrix.sync.aligned.m8n8.x4.shared.b16 {%0,%1,%2,%3}, [%4];"
                 : "=r"(r0), "=r"(r1), "=r"(r2), "=r"(r3) : "r"(a));
}
__device__ __forceinline__ void ldsm_x4_t(uint32_t a, uint32_t& r0, uint32_t& r1,
                                          uint32_t& r2, uint32_t& r3) {
    asm volatile("ldmatrix.sync.aligned.m8n8.x4.trans.shared.b16 {%0,%1,%2,%3}, [%4];"
                 : "=r"(r0), "=r"(r1), "=r"(r2), "=r"(r3) : "r"(a));
}
__device__ __forceinline__ void mma_bf16(float c[4], const uint32_t a[4],
                                         uint32_t b0, uint32_t b1) {
    asm volatile(
        "mma.sync.aligned.m16n8k16.row.col.f32.bf16.bf16.f32 "
        "{%0,%1,%2,%3}, {%4,%5,%6,%7}, {%8,%9}, {%0,%1,%2,%3};"
        : "+f"(c[0]), "+f"(c[1]), "+f"(c[2]), "+f"(c[3])
        : "r"(a[0]), "r"(a[1]), "r"(a[2]), "r"(a[3]), "r"(b0), "r"(b1));
}

// SMEM geometry: A tile 128x64 (stride 72), B tiles 3x 64x128 (stride 136).
#define AS_STRIDE 72
#define BS_STRIDE 136
#define AS_ELEMS  (128 * AS_STRIDE)
#define BS_ELEMS  (64 * BS_STRIDE)
#define MMA_SMEM_BYTES ((AS_ELEMS + 3 * BS_ELEMS) * 2)

// ---------------------------------------------------------------------------
// Hidden GEMM: wx[b,j] = sum_i X[b,i]*W[i,j] + bh[j]   (M=128,N=128,K=4096)
// grid = B/128, 256 thr = 8 warps (4 m-warps x 2 n-warps, warp tile 32x64)
// ---------------------------------------------------------------------------
__global__ void __launch_bounds__(256, 2)
rbm_hidden_mma(int useX0, const float* __restrict__ bh,
               uint32_t k0, uint32_t k1, int doSample, int accIdx) {
    extern __shared__ __align__(16) __nv_bfloat16 sm[];
    __nv_bfloat16* As = sm;
    __nv_bfloat16* Bs = sm + AS_ELEMS;
    __shared__ float bias_s[128];

    const __nv_bfloat16* __restrict__ X = useX0 ? g_xb : g_xi;
    const int tid = threadIdx.x;
    const int lane = tid & 31, w = tid >> 5;
    const int wm = w & 3, wn = w >> 2;
    const int b0 = blockIdx.x * 128;
    if (tid < 128) bias_s[tid] = bh[tid];

    float acc[2][8][4];
    #pragma unroll
    for (int mt = 0; mt < 2; mt++)
        #pragma unroll
        for (int nt = 0; nt < 8; nt++)
            #pragma unroll
            for (int e = 0; e < 4; e++) acc[mt][nt][e] = 0.0f;

    const uint32_t As_u = smem_u32(As);
    const uint32_t Bs_u = smem_u32(Bs);
    const uint32_t a_off = ((wm * 32 + (lane & 15)) * AS_STRIDE + (lane >> 4) * 8) * 2;
    const uint32_t b_off = ((lane & 15) * BS_STRIDE + wn * 64 + (lane >> 4) * 8) * 2;

    for (int kc = 0; kc < RBM_D; kc += 64) {
        __syncthreads();
        #pragma unroll
        for (int p = 0; p < 4; ++p) {
            int lin = tid + p * 256;
            int row = lin >> 3, seg = lin & 7;
            *(uint4*)&As[row * AS_STRIDE + seg * 8] =
                *(const uint4*)&X[(size_t)(b0 + row) * RBM_D + kc + seg * 8];
        }
        #pragma unroll
        for (int part = 0; part < 3; ++part) {
            #pragma unroll
            for (int p = 0; p < 4; ++p) {
                int lin = tid + p * 256;
                int row = lin >> 4, seg = lin & 15;
                *(uint4*)&Bs[part * BS_ELEMS + row * BS_STRIDE + seg * 8] =
                    *(const uint4*)&g_Wp[part][(size_t)(kc + row) * RBM_H + seg * 8];
            }
        }
        __syncthreads();
        #pragma unroll
        for (int ks = 0; ks < 4; ++ks) {
            uint32_t a[2][4];
            #pragma unroll
            for (int mt = 0; mt < 2; ++mt)
                ldsm_x4(As_u + a_off + (mt * 16 * AS_STRIDE + ks * 16) * 2,
                        a[mt][0], a[mt][1], a[mt][2], a[mt][3]);
            #pragma unroll
            for (int part = 0; part < 3; ++part) {
                #pragma unroll
                for (int np = 0; np < 4; ++np) {
                    uint32_t r0, r1, r2, r3;
                    ldsm_x4_t(Bs_u + (part * BS_ELEMS) * 2 + b_off +
                              (ks * 16 * BS_STRIDE + np * 16) * 2, r0, r1, r2, r3);
                    mma_bf16(acc[0][np * 2],     a[0], r0, r1);
                    mma_bf16(acc[0][np * 2 + 1], a[0], r2, r3);
                    mma_bf16(acc[1][np * 2],     a[1], r0, r1);
                    mma_bf16(acc[1][np * 2 + 1], a[1], r2, r3);
                }
            }
        }
    }

    // epilogue: sample h / accumulate softplus
    const __nv_bfloat16 one = __float2bfloat16(1.0f);
    const __nv_bfloat16 zero = __float2bfloat16(0.0f);
    float fe = 0.0f;
    #pragma unroll
    for (int mt = 0; mt < 2; ++mt) {
        #pragma unroll
        for (int nt = 0; nt < 8; ++nt) {
            int row0 = b0 + wm * 32 + mt * 16 + (lane >> 2);
            int col0 = wn * 64 + nt * 8 + (lane & 3) * 2;
            #pragma unroll
            for (int half = 0; half < 2; ++half) {
                int row = row0 + half * 8;
                float wx0 = acc[mt][nt][half * 2 + 0] + bias_s[col0];
                float wx1 = acc[mt][nt][half * 2 + 1] + bias_s[col0 + 1];
                if (doSample) {
                    float u0 = tf_uniform(k0, k1, (uint32_t)(row * RBM_H + col0));
                    float u1 = tf_uniform(k0, k1, (uint32_t)(row * RBM_H + col0 + 1));
                    __nv_bfloat162 v;
                    v.x = (u0 < sigmoid_f(wx0)) ? one : zero;
                    v.y = (u1 < sigmoid_f(wx1)) ? one : zero;
                    *(__nv_bfloat162*)&g_h[(size_t)row * RBM_H + col0] = v;
                }
                if (accIdx >= 0) fe += softplus_f(wx0) + softplus_f(wx1);
            }
        }
    }
    if (accIdx >= 0) block_acc_add(fe, accIdx);
}

// ---------------------------------------------------------------------------
// Visible GEMM: wx[b,d] = sum_j h[b,j]*Wt[j,d] + bx[d]  (M=128,N=128,K=128)
// grid = (D/128, B/128)
// ---------------------------------------------------------------------------
__global__ void __launch_bounds__(256, 2)
rbm_visible_mma(const float* __restrict__ bx, uint32_t k0, uint32_t k1) {
    extern __shared__ __align__(16) __nv_bfloat16 sm[];
    __nv_bfloat16* As = sm;
    __nv_bfloat16* Bs = sm + AS_ELEMS;
    __shared__ float bias_s[128];

    const int tid = threadIdx.x;
    const int lane = tid & 31, w = tid >> 5;
    const int wm = w & 3, wn = w >> 2;
    const int d0 = blockIdx.x * 128;
    const int b0 = blockIdx.y * 128;
    if (tid < 128) bias_s[tid] = bx[d0 + tid];

    float acc[2][8][4];
    #pragma unroll
    for (int mt = 0; mt < 2; mt++)
        #pragma unroll
        for (int nt = 0; nt < 8; nt++)
            #pragma unroll
            for (int e = 0; e < 4; e++) acc[mt][nt][e] = 0.0f;

    const uint32_t As_u = smem_u32(As);
    const uint32_t Bs_u = smem_u32(Bs);
    const uint32_t a_off = ((wm * 32 + (lane & 15)) * AS_STRIDE + (lane >> 4) * 8) * 2;
    const uint32_t b_off = ((lane & 15) * BS_STRIDE + wn * 64 + (lane >> 4) * 8) * 2;

    #pragma unroll
    for (int kc = 0; kc < RBM_H; kc += 64) {
        __syncthreads();
        #pragma unroll
        for (int p = 0; p < 4; ++p) {
            int lin = tid + p * 256;
            int row = lin >> 3, seg = lin & 7;
            *(uint4*)&As[row * AS_STRIDE + seg * 8] =
                *(const uint4*)&g_h[(size_t)(b0 + row) * RBM_H + kc + seg * 8];
        }
        #pragma unroll
        for (int part = 0; part < 3; ++part) {
            #pragma unroll
            for (int p = 0; p < 4; ++p) {
                int lin = tid + p * 256;
                int row = lin >> 4, seg = lin & 15;
                *(uint4*)&Bs[part * BS_ELEMS + row * BS_STRIDE + seg * 8] =
                    *(const uint4*)&g_Wtp[part][(size_t)(kc + row) * RBM_D + d0 + seg * 8];
            }
        }
        __syncthreads();
        #pragma unroll
        for (int ks = 0; ks < 4; ++ks) {
            uint32_t a[2][4];
            #pragma unroll
            for (int mt = 0; mt < 2; ++mt)
                ldsm_x4(As_u + a_off + (mt * 16 * AS_STRIDE + ks * 16) * 2,
                        a[mt][0], a[mt][1], a[mt][2], a[mt][3]);
            #pragma unroll
            for (int part = 0; part < 3; ++part) {
                #pragma unroll
                for (int np = 0; np < 4; ++np) {
                    uint32_t r0, r1, r2, r3;
                    ldsm_x4_t(Bs_u + (part * BS_ELEMS) * 2 + b_off +
                              (ks * 16 * BS_STRIDE + np * 16) * 2, r0, r1, r2, r3);
                    mma_bf16(acc[0][np * 2],     a[0], r0, r1);
                    mma_bf16(acc[0][np * 2 + 1], a[0], r2, r3);
                    mma_bf16(acc[1][np * 2],     a[1], r0, r1);
                    mma_bf16(acc[1][np * 2 + 1], a[1], r2, r3);
                }
            }
        }
    }

    // epilogue: sample xi
    const __nv_bfloat16 one = __float2bfloat16(1.0f);
    const __nv_bfloat16 zero = __float2bfloat16(0.0f);
    #pragma unroll
    for (int mt = 0; mt < 2; ++mt) {
        #pragma unroll
        for (int nt = 0; nt < 8; ++nt) {
            int row0 = b0 + wm * 32 + mt * 16 + (lane >> 2);
            int col0 = wn * 64 + nt * 8 + (lane & 3) * 2;
            #pragma unroll
            for (int half = 0; half < 2; ++half) {
                int b = row0 + half * 8;
                int d = d0 + col0;
                float wx0 = acc[mt][nt][half * 2 + 0] + bias_s[col0];
                float wx1 = acc[mt][nt][half * 2 + 1] + bias_s[col0 + 1];
                uint32_t base = (uint32_t)b * (uint32_t)RBM_D + (uint32_t)d;
                float u0 = tf_uniform(k0, k1, base);
                float u1 = tf_uniform(k0, k1, base + 1u);
                __nv_bfloat162 v;
                v.x = (u0 < sigmoid_f(wx0)) ? one : zero;
                v.y = (u1 < sigmoid_f(wx1)) ? one : zero;
                *(__nv_bfloat162*)&g_xi[(size_t)b * RBM_D + d] = v;
            }
        }
    }
}

// ---------------------------------------------------------------------------
// Prep: exact 3-term bf16 split of W (+ transpose);  x -> bf16
// ---------------------------------------------------------------------------
__global__ void __launch_bounds__(256)
rbm_prep_w(const float* __restrict__ W) {
    int i = blockIdx.x * 256 + threadIdx.x;
    if (i >= RBM_D * RBM_H) return;
    float w = W[i];
    __nv_bfloat16 h1 = __float2bfloat16(w);
    float r1 = w - __bfloat162float(h1);
    __nv_bfloat16 h2 = __float2bfloat16(r1);
    float r2 = r1 - __bfloat162float(h2);
    __nv_bfloat16 h3 = __float2bfloat16(r2);
    g_Wp[0][i] = h1; g_Wp[1][i] = h2; g_Wp[2][i] = h3;
    int r = i >> 7, c = i & 127;
    size_t t = (size_t)c * RBM_D + r;
    g_Wtp[0][t] = h1; g_Wtp[1][t] = h2; g_Wtp[2][t] = h3;
}

__global__ void __launch_bounds__(256)
rbm_convert_x(const float* __restrict__ x) {
    size_t i = ((size_t)blockIdx.x * 256 + threadIdx.x) * 8;
    float4 f0 = *(const float4*)&x[i];
    float4 f1 = *(const float4*)&x[i + 4];
    __nv_bfloat162 r0 = __floats2bfloat162_rn(f0.x, f0.y);
    __nv_bfloat162 r1 = __floats2bfloat162_rn(f0.z, f0.w);
    __nv_bfloat162 r2 = __floats2bfloat162_rn(f1.x, f1.y);
    __nv_bfloat162 r3 = __floats2bfloat162_rn(f1.z, f1.w);
    uint4 o;
    o.x = *(uint32_t*)&r0; o.y = *(uint32_t*)&r1;
    o.z = *(uint32_t*)&r2; o.w = *(uint32_t*)&r3;
    *(uint4*)&g_xb[i] = o;
}

// ---------------------------------------------------------------------------
// Bias dot terms
// ---------------------------------------------------------------------------
__global__ void __launch_bounds__(256)
rbm_dotbx_f32(const float* __restrict__ v, const float* __restrict__ bx, int slot) {
    const size_t total = (size_t)RBM_B * RBM_D;
    float local = 0.0f;
    for (size_t i = (size_t)blockIdx.x * blockDim.x + threadIdx.x;
         i < total; i += (size_t)gridDim.x * blockDim.x)
        local += v[i] * bx[i & (RBM_D - 1)];
    block_acc_add(local, slot);
}
__global__ void __launch_bounds__(256)
rbm_dotbx_bf16(const float* __restrict__ bx, int slot) {
    const size_t total2 = (size_t)RBM_B * RBM_D / 2;
    const __nv_bfloat162* v = (const __nv_bfloat162*)g_xi;
    float local = 0.0f;
    for (size_t i = (size_t)blockIdx.x * blockDim.x + threadIdx.x;
         i < total2; i += (size_t)gridDim.x * blockDim.x) {
        __nv_bfloat162 p = v[i];
        uint32_t base = (uint32_t)((i * 2) & (RBM_D - 1));
        local += __bfloat162float(p.x) * bx[base] + __bfloat162float(p.y) * bx[base + 1];
    }
    block_acc_add(local, slot);
}

__global__ void rbm_init_kernel() {
    if (threadIdx.x < 4) g_acc[threadIdx.x] = 0.0;
}
__global__ void rbm_final_kernel(float* out) {
    out[0] = (float)((g_acc[1] + g_acc[3] - g_acc[0] - g_acc[2]) * (1.0 / (double)RBM_B));
}

// ---------------------------------------------------------------------------
// Host threefry for fold_in subkeys
// ---------------------------------------------------------------------------
static inline uint32_t h_rotl(uint32_t v, int r) { return (v << r) | (v >> (32 - r)); }
static void h_tf2x32(uint32_t k0, uint32_t k1, uint32_t x0, uint32_t x1,
                     uint32_t* o0, uint32_t* o1) {
    uint32_t ks2 = k0 ^ k1 ^ 0x1BD11BDAu;
    x0 += k0; x1 += k1;
    static const int R0[4] = {13, 15, 26, 6}, R1[4] = {17, 29, 16, 24};
    auto round4 = [&](const int* R) {
        for (int i = 0; i < 4; i++) { x0 += x1; x1 = h_rotl(x1, R[i]); x1 ^= x0; }
    };
    round4(R0); x0 += k1;  x1 += ks2 + 1u;
    round4(R1); x0 += ks2; x1 += k0  + 2u;
    round4(R0); x0 += k0;  x1 += k1  + 3u;
    round4(R1); x0 += k1;  x1 += ks2 + 4u;
    round4(R0); x0 += ks2; x1 += k0  + 5u;
    *o0 = x0; *o1 = x1;
}

extern "C" void kernel_launch(void* const* d_in, const int* in_sizes, int n_in,
                              void* d_out, int out_size) {
    const float* x  = (const float*)d_in[0];   // [B, D]
    const float* W  = (const float*)d_in[1];   // [D, H]
    const float* bx = (const float*)d_in[2];   // [D]
    const float* bh = (const float*)d_in[3];   // [H]
    const int NSTEP = 4;
    float* out = (float*)d_out;

    cudaFuncSetAttribute(rbm_hidden_mma,
        cudaFuncAttributeMaxDynamicSharedMemorySize, MMA_SMEM_BYTES);
    cudaFuncSetAttribute(rbm_visible_mma,
        cudaFuncAttributeMaxDynamicSharedMemorySize, MMA_SMEM_BYTES);

    uint32_t kk[8][2];
    for (int i = 0; i < 2 * NSTEP; i++)
        h_tf2x32(0u, 42u, 0u, (uint32_t)i, &kk[i][0], &kk[i][1]);

    dim3 hgrd(RBM_B / 128);
    dim3 vgrd(RBM_D / 128, RBM_B / 128);

    rbm_init_kernel<<<1, 32>>>();
    rbm_prep_w<<<(RBM_D * RBM_H) / 256, 256>>>(W);
    rbm_convert_x<<<(int)(((size_t)RBM_B * RBM_D / 8) / 256), 256>>>(x);

    // step 0: hidden from x (bf16 copy), sample h, accumulate F(x) softplus
    rbm_hidden_mma<<<hgrd, 256, MMA_SMEM_BYTES>>>(1, bh, kk[0][0], kk[0][1], 1, 0);
    rbm_visible_mma<<<vgrd, 256, MMA_SMEM_BYTES>>>(bx, kk[1][0], kk[1][1]);
    for (int s = 1; s < NSTEP; s++) {
        rbm_hidden_mma<<<hgrd, 256, MMA_SMEM_BYTES>>>(0, bh, kk[2 * s][0], kk[2 * s][1], 1, -1);
        rbm_visible_mma<<<vgrd, 256, MMA_SMEM_BYTES>>>(bx, kk[2 * s + 1][0], kk[2 * s + 1][1]);
    }
    // free energy of x_rec (no sampling)
    rbm_hidden_mma<<<hgrd, 256, MMA_SMEM_BYTES>>>(0, bh, 0u, 0u, 0, 1);
    // bias dot terms
    rbm_dotbx_f32<<<2048, 256>>>(x, bx, 2);
    rbm_dotbx_bf16<<<2048, 256>>>(bx, 3);

    rbm_final_kernel<<<1, 1>>>(out);
}